// round 2
// baseline (speedup 1.0000x reference)
#include <cuda_runtime.h>
#include <cuda_bf16.h>

#define D 128
#define NN 50000
#define NS 20000
#define NE 600000
#define ES 120000

// Scratch (alloc guards forbid cudaMalloc; __device__ globals are the sanctioned path)
__device__ float g_agg[(size_t)NN * D];   // agg / msg (reused)
__device__ float g_h  [(size_t)NN * D];   // x after relu
__device__ float g_h1 [(size_t)NN * D];   // after level 0
__device__ float g_sub [(size_t)NS * D];
__device__ float g_sub2[(size_t)NS * D];

// ---------------------------------------------------------------------------
// Edge scatter: out[sidx[e]] += feat[gidx[e]]   (warp per edge, v4 reductions)
// NOTE: indices are int32 (JAX x64 disabled downgrades int64 -> int32).
// ---------------------------------------------------------------------------
__global__ void scatter_add_k(const float* __restrict__ feat,
                              const int* __restrict__ gidx,
                              const int* __restrict__ sidx,
                              float* __restrict__ out, int nE)
{
    int t = blockIdx.x * blockDim.x + threadIdx.x;
    int e = t >> 5;
    int lane = t & 31;
    if (e >= nE) return;
    int g = gidx[e];
    int s = sidx[e];
    float4 v = reinterpret_cast<const float4*>(feat + (size_t)g * D)[lane];
    float* dst = out + (size_t)s * D + lane * 4;
    asm volatile("red.global.add.v4.f32 [%0], {%1,%2,%3,%4};"
                 :: "l"(dst), "f"(v.x), "f"(v.y), "f"(v.z), "f"(v.w)
                 : "memory");
}

// ---------------------------------------------------------------------------
// y[M,128] = epi( (A (+A2)) @ W + bias (+res) )  fixed N=K=128
// BM=64, BN=128, BK=16, 256 threads, 8x4 outputs/thread
// ---------------------------------------------------------------------------
template<bool RELU, bool HAS_IN2, bool HAS_RES>
__global__ __launch_bounds__(256)
void gemm128(const float* __restrict__ A, const float* __restrict__ A2,
             const float* __restrict__ W, const float* __restrict__ bias,
             const float* __restrict__ res, float* __restrict__ out, int M)
{
    __shared__ float As[16][64];    // transposed: As[k][m]
    __shared__ float Bs[16][128];

    const int tid = threadIdx.x;
    const int tx = tid & 31;        // column group (4 cols each)
    const int ty = tid >> 5;        // row group (8 rows each)
    const int row0 = blockIdx.x * 64;

    float acc[8][4];
    #pragma unroll
    for (int i = 0; i < 8; i++)
        #pragma unroll
        for (int j = 0; j < 4; j++) acc[i][j] = 0.f;

    for (int k0 = 0; k0 < 128; k0 += 16) {
        // --- load A tile (64x16), coalesced float4, add A2 on the fly ---
        {
            int e = tid * 4;            // 0..1023
            int r = e >> 4;             // row within tile
            int k = e & 15;
            int grow = row0 + r;
            float4 v = make_float4(0.f, 0.f, 0.f, 0.f);
            if (grow < M) {
                v = *reinterpret_cast<const float4*>(A + (size_t)grow * 128 + k0 + k);
                if (HAS_IN2) {
                    float4 u = *reinterpret_cast<const float4*>(A2 + (size_t)grow * 128 + k0 + k);
                    v.x += u.x; v.y += u.y; v.z += u.z; v.w += u.w;
                }
            }
            As[k + 0][r] = v.x; As[k + 1][r] = v.y;
            As[k + 2][r] = v.z; As[k + 3][r] = v.w;
        }
        // --- load W tile (16x128), 2x float4 per thread ---
        {
            int e = tid * 4;
            int kk = e >> 7, j = e & 127;
            *reinterpret_cast<float4*>(&Bs[kk][j]) =
                *reinterpret_cast<const float4*>(W + (size_t)(k0 + kk) * 128 + j);
            e += 1024;
            kk = e >> 7; j = e & 127;
            *reinterpret_cast<float4*>(&Bs[kk][j]) =
                *reinterpret_cast<const float4*>(W + (size_t)(k0 + kk) * 128 + j);
        }
        __syncthreads();

        #pragma unroll
        for (int kk = 0; kk < 16; kk++) {
            float a[8], b[4];
            *reinterpret_cast<float4*>(&a[0]) = *reinterpret_cast<float4*>(&As[kk][ty * 8]);
            *reinterpret_cast<float4*>(&a[4]) = *reinterpret_cast<float4*>(&As[kk][ty * 8 + 4]);
            *reinterpret_cast<float4*>(&b[0]) = *reinterpret_cast<float4*>(&Bs[kk][tx * 4]);
            #pragma unroll
            for (int i = 0; i < 8; i++)
                #pragma unroll
                for (int j = 0; j < 4; j++)
                    acc[i][j] += a[i] * b[j];
        }
        __syncthreads();
    }

    // --- epilogue ---
    float4 bv = *reinterpret_cast<const float4*>(bias + tx * 4);
    #pragma unroll
    for (int i = 0; i < 8; i++) {
        int grow = row0 + ty * 8 + i;
        if (grow >= M) break;
        float4 v;
        v.x = acc[i][0] + bv.x; v.y = acc[i][1] + bv.y;
        v.z = acc[i][2] + bv.z; v.w = acc[i][3] + bv.w;
        if (HAS_RES) {
            float4 r = *reinterpret_cast<const float4*>(res + (size_t)grow * 128 + tx * 4);
            v.x += r.x; v.y += r.y; v.z += r.z; v.w += r.w;
        }
        if (RELU) {
            v.x = fmaxf(v.x, 0.f); v.y = fmaxf(v.y, 0.f);
            v.z = fmaxf(v.z, 0.f); v.w = fmaxf(v.w, 0.f);
        }
        *reinterpret_cast<float4*>(out + (size_t)grow * 128 + tx * 4) = v;
    }
}

// ---------------------------------------------------------------------------

extern "C" void kernel_launch(void* const* d_in, const int* in_sizes, int n_in,
                              void* d_out, int out_size)
{
    const float* x     = (const float*)d_in[0];
    const float* Wm    = (const float*)d_in[1];
    const float* bm    = (const float*)d_in[2];
    const float* Wn2s0 = (const float*)d_in[3];
    const float* bn2s0 = (const float*)d_in[4];
    const float* Ws2n0 = (const float*)d_in[5];
    const float* bs2n0 = (const float*)d_in[6];
    const float* Wn2s1 = (const float*)d_in[7];
    const float* bn2s1 = (const float*)d_in[8];
    const float* Ws2n1 = (const float*)d_in[9];
    const float* bs2n1 = (const float*)d_in[10];
    const int* nei = (const int*)d_in[11];   // (2, NE) int32
    const int* r0  = (const int*)d_in[12];
    const int* c0  = (const int*)d_in[13];
    const int* r1  = (const int*)d_in[14];
    const int* c1  = (const int*)d_in[15];
    float* out = (float*)d_out;

    float *agg, *h, *h1, *sub, *sub2;
    cudaGetSymbolAddress((void**)&agg,  g_agg);
    cudaGetSymbolAddress((void**)&h,    g_h);
    cudaGetSymbolAddress((void**)&h1,   g_h1);
    cudaGetSymbolAddress((void**)&sub,  g_sub);
    cudaGetSymbolAddress((void**)&sub2, g_sub2);

    const size_t NB_N = (size_t)NN * D * sizeof(float);
    const size_t NB_S = (size_t)NS * D * sizeof(float);
    const int GB_N = (NN + 63) / 64;   // 782
    const int GB_S = (NS + 63) / 64;   // 313
    const int SC_NE = (NE * 32 + 255) / 256;
    const int SC_ES = (ES * 32 + 255) / 256;

    // --- message_neighbor: agg = scatter_sum(x[src] -> dst); h = relu((x+agg)@Wm+bm)
    cudaMemsetAsync(agg, 0, NB_N);
    scatter_add_k<<<SC_NE, 256>>>(x, nei, nei + NE, agg, NE);
    gemm128<true, true, false><<<GB_N, 256>>>(x, agg, Wm, bm, nullptr, h, NN);

    // --- level 0 ---
    cudaMemsetAsync(sub, 0, NB_S);
    scatter_add_k<<<SC_ES, 256>>>(h, r0, c0, sub, ES);
    gemm128<false, false, false><<<GB_S, 256>>>(sub, nullptr, Wn2s0, bn2s0, nullptr, sub2, NS);
    cudaMemsetAsync(agg, 0, NB_N);   // reuse as msg
    scatter_add_k<<<SC_ES, 256>>>(sub2, c0, r0, agg, ES);
    gemm128<false, false, true><<<GB_N, 256>>>(agg, nullptr, Ws2n0, bs2n0, h, h1, NN);

    // --- level 1 ---
    cudaMemsetAsync(sub, 0, NB_S);
    scatter_add_k<<<SC_ES, 256>>>(h1, r1, c1, sub, ES);
    gemm128<false, false, false><<<GB_S, 256>>>(sub, nullptr, Wn2s1, bn2s1, nullptr, sub2, NS);
    cudaMemsetAsync(agg, 0, NB_N);
    scatter_add_k<<<SC_ES, 256>>>(sub2, c1, r1, agg, ES);
    gemm128<false, false, true><<<GB_N, 256>>>(agg, nullptr, Ws2n1, bs2n1, h1, out, NN);
}